// round 5
// baseline (speedup 1.0000x reference)
#include <cuda_runtime.h>

#define NQ   4
#define DIM  16
#define NH   8
#define NL   2
#define EMB  32
#define NT3  81   // 3^4 basis terms per head
#define BLK  64   // threads per block
#define TPT  4    // tokens per thread

typedef unsigned long long u64;

// Per-head Fourier coefficients: [h][t] -> float4 (ev index 0..3), 16B aligned
__device__ float4 g_C4[NH * NT3];

// ---- packed f32x2 helpers -------------------------------------------------
#define FMAX2(d, a, b, c) \
    asm("fma.rn.f32x2 %0, %1, %2, %3;" : "=l"(d) : "l"(a), "l"(b), "l"(c))
#define MUL2(d, a, b) \
    asm("mul.rn.f32x2 %0, %1, %2;" : "=l"(d) : "l"(a), "l"(b))
#define PACK2(d, lo, hi) \
    asm("mov.b64 %0, {%1, %2};" : "=l"(d) : "f"(lo), "f"(hi))
#define UNPACK2(lo, hi, d) \
    asm("mov.b64 {%0, %1}, %2;" : "=f"(lo), "=f"(hi) : "l"(d))

// ---------------------------------------------------------------------------
// Setup kernel: shuffle-parallel simulation of the fixed per-head unitary.
// 8 blocks x 256 threads; thread (k,m) holds amplitude <m|U|k>.
// ---------------------------------------------------------------------------
__global__ void qc_setup_kernel(const float* __restrict__ params) {
    __shared__ float Vre[DIM][DIM + 1];
    __shared__ float Vim[DIM][DIM + 1];
    __shared__ float Msh[DIM * DIM][4];

    const int h   = blockIdx.x;
    const int tid = threadIdx.x;     // 0..255
    const int m   = tid & 15;        // amplitude index
    const int k   = tid >> 4;        // input basis state

    float re = (k == m) ? 1.f : 0.f;
    float im = 0.f;

    const float* p = params + h * NL * NQ * 3;

    #pragma unroll
    for (int l = 0; l < NL; l++) {
        #pragma unroll
        for (int q = 0; q < NQ; q++) {
            const int mask = 8 >> q;   // qubit 0 = MSB
            float th, c, s, r1, i1;

            // RX
            th = p[(l * NQ + q) * 3 + 0];
            c = cosf(0.5f * th); s = sinf(0.5f * th);
            r1 = __shfl_xor_sync(0xffffffffu, re, mask);
            i1 = __shfl_xor_sync(0xffffffffu, im, mask);
            re = c * re + s * i1;
            im = c * im - s * r1;

            // RY
            th = p[(l * NQ + q) * 3 + 1];
            c = cosf(0.5f * th); s = sinf(0.5f * th);
            r1 = __shfl_xor_sync(0xffffffffu, re, mask);
            i1 = __shfl_xor_sync(0xffffffffu, im, mask);
            {
                const float sgn = (m & mask) ? s : -s;
                re = c * re + sgn * r1;
                im = c * im + sgn * i1;
            }

            // RZ
            th = p[(l * NQ + q) * 3 + 2];
            c = cosf(0.5f * th); s = sinf(0.5f * th);
            {
                const float sg = (m & mask) ? s : -s;
                const float r = re, i = im;
                re = c * r - sg * i;
                im = c * i + sg * r;
            }
        }
        // CNOT chain
        const int cm[4] = {8, 4, 2, 1};
        const int tm[4] = {4, 2, 1, 8};
        #pragma unroll
        for (int e = 0; e < 4; e++) {
            const float r1 = __shfl_xor_sync(0xffffffffu, re, tm[e]);
            const float i1 = __shfl_xor_sync(0xffffffffu, im, tm[e]);
            if (m & cm[e]) { re = r1; im = i1; }
        }
    }

    Vre[k][m] = re;
    Vim[k][m] = im;
    __syncthreads();

    // M_i[k,l] = sum_m z_i(m) Re(conj(V[m,k]) V[m,l])
    {
        const int kk = tid >> 4;
        const int ll = tid & 15;
        float P[DIM];
        float tot = 0.f;
        #pragma unroll
        for (int mm = 0; mm < DIM; mm++) {
            P[mm] = Vre[kk][mm] * Vre[ll][mm] + Vim[kk][mm] * Vim[ll][mm];
            tot += P[mm];
        }
        #pragma unroll
        for (int i = 0; i < 4; i++) {
            float sub = 0.f;
            #pragma unroll
            for (int mm = 0; mm < DIM; mm++)
                if ((mm >> (3 - i)) & 1) sub += P[mm];
            Msh[tid][i] = tot - 2.f * sub;
        }
    }
    __syncthreads();

    // Expand into the 81-term basis via Msh lookups.
    for (int idx = tid; idx < 4 * NT3; idx += blockDim.x) {
        const int i = idx / NT3;
        const int t = idx % NT3;
        const int tq[4] = { t / 27, (t / 9) % 3, (t / 3) % 3, t % 3 };

        float acc = 0.f;
        for (int b = 0; b < 16; b++) {
            int kk = 0, ll = 0;
            float sgn = 1.f / 16.f;
            #pragma unroll
            for (int q = 0; q < 4; q++) {
                const int bq = (b >> q) & 1;
                const int sh = 3 - q;
                if (tq[q] == 2) {
                    kk |= bq << sh; ll |= (1 - bq) << sh;
                } else {
                    kk |= bq << sh; ll |= bq << sh;
                    if (tq[q] == 1 && bq) sgn = -sgn;
                }
            }
            acc += sgn * Msh[kk * DIM + ll][i];
        }
        ((float*)g_C4)[(h * NT3 + t) * 4 + i] = acc;
    }
}

// ---------------------------------------------------------------------------
// Main kernel: 4 tokens/thread, f32x2 packed over ev-index pairs.
// One broadcast LDS.128 of C now feeds 4 tokens (8 FMAX2 = 16 FMAs per
// 16B of smem traffic), halving the L1 broadcast wall vs TPT=2.
// ---------------------------------------------------------------------------
__global__ __launch_bounds__(BLK, 4) void qc_main_kernel(
    const float*  __restrict__ x,
    const float*  __restrict__ W,      // [EMB][NH*NQ] row-major
    const float*  __restrict__ bias,   // [EMB]
    float*        __restrict__ out,
    int ntok)
{
    __shared__ ulonglong2 Cs[NH * NT3];     // (c0,c1),(c2,c3) packed pairs
    __shared__ ulonglong2 Wq[NH * 4 * 8];   // [h][i][k]: ((W[4k],W[4k+1]),(W[4k+2],W[4k+3])) col 4h+i
    __shared__ u64        bs2[16];          // (b[2jp], b[2jp+1])

    const int tid = threadIdx.x;
    for (int i = tid; i < NH * NT3; i += BLK)
        Cs[i] = reinterpret_cast<const ulonglong2*>(g_C4)[i];
    for (int i = tid; i < NH * 4 * 8; i += BLK) {
        const int k = i & 7;
        const int c = i >> 3;     // c = 4h + i_ev
        u64 lo, hi;
        PACK2(lo, W[(4 * k + 0) * EMB + c], W[(4 * k + 1) * EMB + c]);
        PACK2(hi, W[(4 * k + 2) * EMB + c], W[(4 * k + 3) * EMB + c]);
        Wq[i] = make_ulonglong2(lo, hi);
    }
    if (tid < 16) {
        u64 v;
        PACK2(v, bias[2 * tid], bias[2 * tid + 1]);
        bs2[tid] = v;
    }
    __syncthreads();

    const int base = blockIdx.x * (BLK * TPT) + tid;
    int  tok[TPT];
    bool ok[TPT];
    #pragma unroll
    for (int t = 0; t < TPT; t++) { tok[t] = base + t * BLK; ok[t] = tok[t] < ntok; }

    u64 acc[TPT][16];
    #pragma unroll
    for (int t = 0; t < TPT; t++)
        #pragma unroll
        for (int jp = 0; jp < 16; jp++) acc[t][jp] = bs2[jp];

    u64 one2;
    PACK2(one2, 1.0f, 1.0f);

    const float4* xp4 = reinterpret_cast<const float4*>(x);

    #pragma unroll 1
    for (int h = 0; h < NH; h++) {
        const ulonglong2* Ch = Cs + h * NT3;

        // dup-packed trig basis per token: Td[t][q][0]=(cos,cos), [1]=(sin,sin)
        u64 Td[TPT][4][2];
        #pragma unroll
        for (int t = 0; t < TPT; t++) {
            float4 xa = ok[t] ? xp4[(size_t)tok[t] * NH + h]
                              : make_float4(0.f, 0.f, 0.f, 0.f);
            float c, s;
            __sincosf(xa.x, &s, &c); PACK2(Td[t][0][0], c, c); PACK2(Td[t][0][1], s, s);
            __sincosf(xa.y, &s, &c); PACK2(Td[t][1][0], c, c); PACK2(Td[t][1][1], s, s);
            __sincosf(xa.z, &s, &c); PACK2(Td[t][2][0], c, c); PACK2(Td[t][2][1], s, s);
            __sincosf(xa.w, &s, &c); PACK2(Td[t][3][0], c, c); PACK2(Td[t][3][1], s, s);
        }

        u64 ev01[TPT], ev23[TPT];
        #pragma unroll
        for (int t = 0; t < TPT; t++) { ev01[t] = 0ull; ev23[t] = 0ull; }

        int term = 0;
        #pragma unroll
        for (int a = 0; a < 3; a++) {
            u64 p0[TPT];
            #pragma unroll
            for (int t = 0; t < TPT; t++)
                p0[t] = (a > 0) ? Td[t][0][a - 1] : one2;
            #pragma unroll
            for (int b = 0; b < 3; b++) {
                u64 p1[TPT];
                #pragma unroll
                for (int t = 0; t < TPT; t++) {
                    if (b == 0)      p1[t] = p0[t];
                    else if (a == 0) p1[t] = Td[t][1][b - 1];
                    else             MUL2(p1[t], p0[t], Td[t][1][b - 1]);
                }
                #pragma unroll
                for (int c = 0; c < 3; c++) {
                    const bool v2 = (a | b) != 0;
                    u64 p2[TPT];
                    #pragma unroll
                    for (int t = 0; t < TPT; t++) {
                        if (c == 0)      p2[t] = p1[t];
                        else if (!v2)    p2[t] = Td[t][2][c - 1];
                        else             MUL2(p2[t], p1[t], Td[t][2][c - 1]);
                    }
                    #pragma unroll
                    for (int d = 0; d < 3; d++) {
                        const bool v3 = (a | b | c) != 0;
                        const ulonglong2 cc = Ch[term++];
                        #pragma unroll
                        for (int t = 0; t < TPT; t++) {
                            u64 ph;
                            if (d == 0)      ph = p2[t];
                            else if (!v3)    ph = Td[t][3][d - 1];
                            else             MUL2(ph, p2[t], Td[t][3][d - 1]);
                            FMAX2(ev01[t], cc.x, ph, ev01[t]);
                            FMAX2(ev23[t], cc.y, ph, ev23[t]);
                        }
                    }
                }
            }
        }

        // Fold into j-packed accumulators; each W load feeds all 4 tokens.
        u64 dv[TPT][4];
        #pragma unroll
        for (int t = 0; t < TPT; t++) {
            float e0, e1, e2, e3;
            UNPACK2(e0, e1, ev01[t]); UNPACK2(e2, e3, ev23[t]);
            PACK2(dv[t][0], e0, e0); PACK2(dv[t][1], e1, e1);
            PACK2(dv[t][2], e2, e2); PACK2(dv[t][3], e3, e3);
        }
        const ulonglong2* Wh = Wq + h * 32;
        #pragma unroll
        for (int i = 0; i < 4; i++) {
            #pragma unroll
            for (int k = 0; k < 8; k++) {
                const ulonglong2 wd = Wh[i * 8 + k];
                #pragma unroll
                for (int t = 0; t < TPT; t++) {
                    FMAX2(acc[t][2 * k],     wd.x, dv[t][i], acc[t][2 * k]);
                    FMAX2(acc[t][2 * k + 1], wd.y, dv[t][i], acc[t][2 * k + 1]);
                }
            }
        }
    }

    #pragma unroll
    for (int t = 0; t < TPT; t++) {
        if (ok[t]) {
            ulonglong2* op = reinterpret_cast<ulonglong2*>(out + (size_t)tok[t] * EMB);
            #pragma unroll
            for (int jj = 0; jj < 8; jj++)
                op[jj] = make_ulonglong2(acc[t][2 * jj], acc[t][2 * jj + 1]);
        }
    }
}

// ---------------------------------------------------------------------------
extern "C" void kernel_launch(void* const* d_in, const int* in_sizes, int n_in,
                              void* d_out, int out_size) {
    const float* x      = (const float*)d_in[0];
    const float* params = (const float*)d_in[1];
    const float* W      = (const float*)d_in[2];
    const float* b      = (const float*)d_in[3];
    float* out = (float*)d_out;

    const int ntok = in_sizes[0] / EMB;

    qc_setup_kernel<<<NH, 256>>>(params);

    const int tok_per_block = BLK * TPT;
    const int blocks = (ntok + tok_per_block - 1) / tok_per_block;
    qc_main_kernel<<<blocks, BLK>>>(x, W, b, out, ntok);
}

// round 6
// speedup vs baseline: 1.0215x; 1.0215x over previous
#include <cuda_runtime.h>

#define NQ   4
#define DIM  16
#define NH   8
#define NL   2
#define EMB  32
#define NT3  81   // 3^4 basis terms per head
#define BLK  64   // threads per block
#define TPT  4    // tokens per thread

typedef unsigned long long u64;

// Per-head Fourier coefficients: [h][t] -> float4 (ev index 0..3), 16B aligned
__device__ float4 g_C4[NH * NT3];

// ---- packed f32x2 helpers -------------------------------------------------
#define FMAX2(d, a, b, c) \
    asm("fma.rn.f32x2 %0, %1, %2, %3;" : "=l"(d) : "l"(a), "l"(b), "l"(c))
#define MUL2(d, a, b) \
    asm("mul.rn.f32x2 %0, %1, %2;" : "=l"(d) : "l"(a), "l"(b))
#define PACK2(d, lo, hi) \
    asm("mov.b64 %0, {%1, %2};" : "=l"(d) : "f"(lo), "f"(hi))
#define UNPACK2(lo, hi, d) \
    asm("mov.b64 {%0, %1}, %2;" : "=f"(lo), "=f"(hi) : "l"(d))

// ---------------------------------------------------------------------------
// Setup kernel: shuffle-parallel simulation of the fixed per-head unitary.
// 8 blocks x 256 threads; thread (k,m) holds amplitude <m|U|k>.
// ---------------------------------------------------------------------------
__global__ void qc_setup_kernel(const float* __restrict__ params) {
    __shared__ float Vre[DIM][DIM + 1];
    __shared__ float Vim[DIM][DIM + 1];
    __shared__ float Msh[DIM * DIM][4];

    const int h   = blockIdx.x;
    const int tid = threadIdx.x;     // 0..255
    const int m   = tid & 15;        // amplitude index
    const int k   = tid >> 4;        // input basis state

    float re = (k == m) ? 1.f : 0.f;
    float im = 0.f;

    const float* p = params + h * NL * NQ * 3;

    #pragma unroll
    for (int l = 0; l < NL; l++) {
        #pragma unroll
        for (int q = 0; q < NQ; q++) {
            const int mask = 8 >> q;   // qubit 0 = MSB
            float th, c, s, r1, i1;

            // RX
            th = p[(l * NQ + q) * 3 + 0];
            c = cosf(0.5f * th); s = sinf(0.5f * th);
            r1 = __shfl_xor_sync(0xffffffffu, re, mask);
            i1 = __shfl_xor_sync(0xffffffffu, im, mask);
            re = c * re + s * i1;
            im = c * im - s * r1;

            // RY
            th = p[(l * NQ + q) * 3 + 1];
            c = cosf(0.5f * th); s = sinf(0.5f * th);
            r1 = __shfl_xor_sync(0xffffffffu, re, mask);
            i1 = __shfl_xor_sync(0xffffffffu, im, mask);
            {
                const float sgn = (m & mask) ? s : -s;
                re = c * re + sgn * r1;
                im = c * im + sgn * i1;
            }

            // RZ
            th = p[(l * NQ + q) * 3 + 2];
            c = cosf(0.5f * th); s = sinf(0.5f * th);
            {
                const float sg = (m & mask) ? s : -s;
                const float r = re, i = im;
                re = c * r - sg * i;
                im = c * i + sg * r;
            }
        }
        // CNOT chain
        const int cm[4] = {8, 4, 2, 1};
        const int tm[4] = {4, 2, 1, 8};
        #pragma unroll
        for (int e = 0; e < 4; e++) {
            const float r1 = __shfl_xor_sync(0xffffffffu, re, tm[e]);
            const float i1 = __shfl_xor_sync(0xffffffffu, im, tm[e]);
            if (m & cm[e]) { re = r1; im = i1; }
        }
    }

    Vre[k][m] = re;
    Vim[k][m] = im;
    __syncthreads();

    // M_i[k,l] = sum_m z_i(m) Re(conj(V[m,k]) V[m,l])
    {
        const int kk = tid >> 4;
        const int ll = tid & 15;
        float P[DIM];
        float tot = 0.f;
        #pragma unroll
        for (int mm = 0; mm < DIM; mm++) {
            P[mm] = Vre[kk][mm] * Vre[ll][mm] + Vim[kk][mm] * Vim[ll][mm];
            tot += P[mm];
        }
        #pragma unroll
        for (int i = 0; i < 4; i++) {
            float sub = 0.f;
            #pragma unroll
            for (int mm = 0; mm < DIM; mm++)
                if ((mm >> (3 - i)) & 1) sub += P[mm];
            Msh[tid][i] = tot - 2.f * sub;
        }
    }
    __syncthreads();

    // Expand into the 81-term basis via Msh lookups.
    for (int idx = tid; idx < 4 * NT3; idx += blockDim.x) {
        const int i = idx / NT3;
        const int t = idx % NT3;
        const int tq[4] = { t / 27, (t / 9) % 3, (t / 3) % 3, t % 3 };

        float acc = 0.f;
        for (int b = 0; b < 16; b++) {
            int kk = 0, ll = 0;
            float sgn = 1.f / 16.f;
            #pragma unroll
            for (int q = 0; q < 4; q++) {
                const int bq = (b >> q) & 1;
                const int sh = 3 - q;
                if (tq[q] == 2) {
                    kk |= bq << sh; ll |= (1 - bq) << sh;
                } else {
                    kk |= bq << sh; ll |= bq << sh;
                    if (tq[q] == 1 && bq) sgn = -sgn;
                }
            }
            acc += sgn * Msh[kk * DIM + ll][i];
        }
        ((float*)g_C4)[(h * NT3 + t) * 4 + i] = acc;
    }
}

// ---------------------------------------------------------------------------
// Main kernel: 4 tokens/thread, f32x2 packed over ev-index pairs, with a
// depth-2 software pipeline on the broadcast C loads so the LDS latency
// (~29-40 cyc) is covered by the 8 FMAX2 of the two in-flight terms.
// x for head h+1 is LDG-prefetched above the 81-term loop of head h.
// ---------------------------------------------------------------------------
__global__ __launch_bounds__(BLK, 4) void qc_main_kernel(
    const float*  __restrict__ x,
    const float*  __restrict__ W,      // [EMB][NH*NQ] row-major
    const float*  __restrict__ bias,   // [EMB]
    float*        __restrict__ out,
    int ntok)
{
    __shared__ ulonglong2 Cs[NH * NT3];     // (c0,c1),(c2,c3) packed pairs
    __shared__ ulonglong2 Wq[NH * 4 * 8];   // [h][i][k]: ((W[4k],W[4k+1]),(W[4k+2],W[4k+3])) col 4h+i
    __shared__ u64        bs2[16];          // (b[2jp], b[2jp+1])

    const int tid = threadIdx.x;
    for (int i = tid; i < NH * NT3; i += BLK)
        Cs[i] = reinterpret_cast<const ulonglong2*>(g_C4)[i];
    for (int i = tid; i < NH * 4 * 8; i += BLK) {
        const int k = i & 7;
        const int c = i >> 3;     // c = 4h + i_ev
        u64 lo, hi;
        PACK2(lo, W[(4 * k + 0) * EMB + c], W[(4 * k + 1) * EMB + c]);
        PACK2(hi, W[(4 * k + 2) * EMB + c], W[(4 * k + 3) * EMB + c]);
        Wq[i] = make_ulonglong2(lo, hi);
    }
    if (tid < 16) {
        u64 v;
        PACK2(v, bias[2 * tid], bias[2 * tid + 1]);
        bs2[tid] = v;
    }
    __syncthreads();

    const int base = blockIdx.x * (BLK * TPT) + tid;
    int  tok[TPT];
    bool ok[TPT];
    #pragma unroll
    for (int t = 0; t < TPT; t++) { tok[t] = base + t * BLK; ok[t] = tok[t] < ntok; }

    u64 acc[TPT][16];
    #pragma unroll
    for (int t = 0; t < TPT; t++)
        #pragma unroll
        for (int jp = 0; jp < 16; jp++) acc[t][jp] = bs2[jp];

    u64 one2;
    PACK2(one2, 1.0f, 1.0f);

    const float4* xp4 = reinterpret_cast<const float4*>(x);

    // prefetch x for head 0
    float4 xnext[TPT];
    #pragma unroll
    for (int t = 0; t < TPT; t++)
        xnext[t] = ok[t] ? xp4[(size_t)tok[t] * NH + 0]
                         : make_float4(0.f, 0.f, 0.f, 0.f);

    #pragma unroll 1
    for (int h = 0; h < NH; h++) {
        const ulonglong2* Ch = Cs + h * NT3;

        // trig for this head from the prefetched x
        u64 Td[TPT][4][2];
        #pragma unroll
        for (int t = 0; t < TPT; t++) {
            const float4 xa = xnext[t];
            float c, s;
            __sincosf(xa.x, &s, &c); PACK2(Td[t][0][0], c, c); PACK2(Td[t][0][1], s, s);
            __sincosf(xa.y, &s, &c); PACK2(Td[t][1][0], c, c); PACK2(Td[t][1][1], s, s);
            __sincosf(xa.z, &s, &c); PACK2(Td[t][2][0], c, c); PACK2(Td[t][2][1], s, s);
            __sincosf(xa.w, &s, &c); PACK2(Td[t][3][0], c, c); PACK2(Td[t][3][1], s, s);
        }

        // LDG-prefetch x for the next head; latency hidden by the 81-term loop
        if (h + 1 < NH) {
            #pragma unroll
            for (int t = 0; t < TPT; t++)
                if (ok[t]) xnext[t] = xp4[(size_t)tok[t] * NH + (h + 1)];
        }

        u64 ev01[TPT], ev23[TPT];
        #pragma unroll
        for (int t = 0; t < TPT; t++) { ev01[t] = 0ull; ev23[t] = 0ull; }

        // depth-2 rolling buffer for the broadcast C loads
        ulonglong2 ccbuf[2];
        ccbuf[0] = Ch[0];
        ccbuf[1] = Ch[1];

        int term = 0;
        #pragma unroll
        for (int a = 0; a < 3; a++) {
            u64 p0[TPT];
            #pragma unroll
            for (int t = 0; t < TPT; t++)
                p0[t] = (a > 0) ? Td[t][0][a - 1] : one2;
            #pragma unroll
            for (int b = 0; b < 3; b++) {
                u64 p1[TPT];
                #pragma unroll
                for (int t = 0; t < TPT; t++) {
                    if (b == 0)      p1[t] = p0[t];
                    else if (a == 0) p1[t] = Td[t][1][b - 1];
                    else             MUL2(p1[t], p0[t], Td[t][1][b - 1]);
                }
                #pragma unroll
                for (int c = 0; c < 3; c++) {
                    const bool v2 = (a | b) != 0;
                    u64 p2[TPT];
                    #pragma unroll
                    for (int t = 0; t < TPT; t++) {
                        if (c == 0)      p2[t] = p1[t];
                        else if (!v2)    p2[t] = Td[t][2][c - 1];
                        else             MUL2(p2[t], p1[t], Td[t][2][c - 1]);
                    }
                    #pragma unroll
                    for (int d = 0; d < 3; d++) {
                        const bool v3 = (a | b | c) != 0;
                        // consume coefficient loaded 2 iterations ago,
                        // refill the slot with term+2 (software pipeline)
                        const ulonglong2 cc = ccbuf[term & 1];
                        if (term + 2 < NT3)
                            ccbuf[term & 1] = Ch[term + 2];
                        #pragma unroll
                        for (int t = 0; t < TPT; t++) {
                            u64 ph;
                            if (d == 0)      ph = p2[t];
                            else if (!v3)    ph = Td[t][3][d - 1];
                            else             MUL2(ph, p2[t], Td[t][3][d - 1]);
                            FMAX2(ev01[t], cc.x, ph, ev01[t]);
                            FMAX2(ev23[t], cc.y, ph, ev23[t]);
                        }
                        term++;
                    }
                }
            }
        }

        // Fold into j-packed accumulators; each W load feeds all 4 tokens.
        u64 dv[TPT][4];
        #pragma unroll
        for (int t = 0; t < TPT; t++) {
            float e0, e1, e2, e3;
            UNPACK2(e0, e1, ev01[t]); UNPACK2(e2, e3, ev23[t]);
            PACK2(dv[t][0], e0, e0); PACK2(dv[t][1], e1, e1);
            PACK2(dv[t][2], e2, e2); PACK2(dv[t][3], e3, e3);
        }
        const ulonglong2* Wh = Wq + h * 32;
        #pragma unroll
        for (int i = 0; i < 4; i++) {
            #pragma unroll
            for (int k = 0; k < 8; k++) {
                const ulonglong2 wd = Wh[i * 8 + k];
                #pragma unroll
                for (int t = 0; t < TPT; t++) {
                    FMAX2(acc[t][2 * k],     wd.x, dv[t][i], acc[t][2 * k]);
                    FMAX2(acc[t][2 * k + 1], wd.y, dv[t][i], acc[t][2 * k + 1]);
                }
            }
        }
    }

    #pragma unroll
    for (int t = 0; t < TPT; t++) {
        if (ok[t]) {
            ulonglong2* op = reinterpret_cast<ulonglong2*>(out + (size_t)tok[t] * EMB);
            #pragma unroll
            for (int jj = 0; jj < 8; jj++)
                op[jj] = make_ulonglong2(acc[t][2 * jj], acc[t][2 * jj + 1]);
        }
    }
}

// ---------------------------------------------------------------------------
extern "C" void kernel_launch(void* const* d_in, const int* in_sizes, int n_in,
                              void* d_out, int out_size) {
    const float* x      = (const float*)d_in[0];
    const float* params = (const float*)d_in[1];
    const float* W      = (const float*)d_in[2];
    const float* b      = (const float*)d_in[3];
    float* out = (float*)d_out;

    const int ntok = in_sizes[0] / EMB;

    qc_setup_kernel<<<NH, 256>>>(params);

    const int tok_per_block = BLK * TPT;
    const int blocks = (ntok + tok_per_block - 1) / tok_per_block;
    qc_main_kernel<<<blocks, BLK>>>(x, W, b, out, ntok);
}

// round 7
// speedup vs baseline: 1.1289x; 1.1051x over previous
#include <cuda_runtime.h>

#define NQ   4
#define DIM  16
#define NH   8
#define NL   2
#define EMB  32
#define NT3  81   // 3^4 basis terms per head
#define BLK  128  // threads per block
#define TPT  2    // tokens per thread

typedef unsigned long long u64;

// ---- packed f32x2 helpers -------------------------------------------------
#define FMAX2(d, a, b, c) \
    asm("fma.rn.f32x2 %0, %1, %2, %3;" : "=l"(d) : "l"(a), "l"(b), "l"(c))
#define MUL2(d, a, b) \
    asm("mul.rn.f32x2 %0, %1, %2;" : "=l"(d) : "l"(a), "l"(b))
#define PACK2(d, lo, hi) \
    asm("mov.b64 %0, {%1, %2};" : "=l"(d) : "f"(lo), "f"(hi))
#define UNPACK2(lo, hi, d) \
    asm("mov.b64 {%0, %1}, %2;" : "=f"(lo), "=f"(hi) : "l"(d))

// All warp-uniform tables live in ONE blob: computed into __device__ memory by
// the setup kernel, then memcpy'd (D2D, graph-capturable) into __constant__.
struct __align__(16) CBlob {
    ulonglong2 C[NH * NT3];   // [h][t]: packed ((c0,c1),(c2,c3))
    ulonglong2 Wq[NH * 32];   // [h][i][k]: ((W[4k],W[4k+1]),(W[4k+2],W[4k+3])) col 4h+i
    u64        b2[16];        // (b[2j], b[2j+1])
};
__device__   CBlob g_blob;
__constant__ CBlob c_blob;

// ---------------------------------------------------------------------------
// Setup kernel: shuffle-parallel simulation of the fixed per-head unitary.
// 8 blocks x 256 threads; thread (k,m) holds amplitude <m|U|k>.
// Block 0 additionally packs W and bias into the blob.
// ---------------------------------------------------------------------------
__global__ void qc_setup_kernel(const float* __restrict__ params,
                                const float* __restrict__ W,
                                const float* __restrict__ bias) {
    __shared__ float Vre[DIM][DIM + 1];
    __shared__ float Vim[DIM][DIM + 1];
    __shared__ float Msh[DIM * DIM][4];

    const int h   = blockIdx.x;
    const int tid = threadIdx.x;     // 0..255
    const int m   = tid & 15;        // amplitude index
    const int k   = tid >> 4;        // input basis state

    // Block 0: pack W (fold layout) and bias.
    if (h == 0) {
        const int kk = tid & 7;
        const int c  = tid >> 3;     // c = 4h + i_ev in [0,32)
        u64 lo, hi;
        PACK2(lo, W[(4 * kk + 0) * EMB + c], W[(4 * kk + 1) * EMB + c]);
        PACK2(hi, W[(4 * kk + 2) * EMB + c], W[(4 * kk + 3) * EMB + c]);
        g_blob.Wq[tid] = make_ulonglong2(lo, hi);
        if (tid < 16) {
            u64 v;
            PACK2(v, bias[2 * tid], bias[2 * tid + 1]);
            g_blob.b2[tid] = v;
        }
    }

    float re = (k == m) ? 1.f : 0.f;
    float im = 0.f;

    const float* p = params + h * NL * NQ * 3;

    #pragma unroll
    for (int l = 0; l < NL; l++) {
        #pragma unroll
        for (int q = 0; q < NQ; q++) {
            const int mask = 8 >> q;   // qubit 0 = MSB
            float th, c, s, r1, i1;

            // RX
            th = p[(l * NQ + q) * 3 + 0];
            c = cosf(0.5f * th); s = sinf(0.5f * th);
            r1 = __shfl_xor_sync(0xffffffffu, re, mask);
            i1 = __shfl_xor_sync(0xffffffffu, im, mask);
            re = c * re + s * i1;
            im = c * im - s * r1;

            // RY
            th = p[(l * NQ + q) * 3 + 1];
            c = cosf(0.5f * th); s = sinf(0.5f * th);
            r1 = __shfl_xor_sync(0xffffffffu, re, mask);
            i1 = __shfl_xor_sync(0xffffffffu, im, mask);
            {
                const float sgn = (m & mask) ? s : -s;
                re = c * re + sgn * r1;
                im = c * im + sgn * i1;
            }

            // RZ
            th = p[(l * NQ + q) * 3 + 2];
            c = cosf(0.5f * th); s = sinf(0.5f * th);
            {
                const float sg = (m & mask) ? s : -s;
                const float r = re, i = im;
                re = c * r - sg * i;
                im = c * i + sg * r;
            }
        }
        // CNOT chain
        const int cm[4] = {8, 4, 2, 1};
        const int tm[4] = {4, 2, 1, 8};
        #pragma unroll
        for (int e = 0; e < 4; e++) {
            const float r1 = __shfl_xor_sync(0xffffffffu, re, tm[e]);
            const float i1 = __shfl_xor_sync(0xffffffffu, im, tm[e]);
            if (m & cm[e]) { re = r1; im = i1; }
        }
    }

    Vre[k][m] = re;
    Vim[k][m] = im;
    __syncthreads();

    // M_i[k,l] = sum_m z_i(m) Re(conj(V[m,k]) V[m,l])
    {
        const int kk = tid >> 4;
        const int ll = tid & 15;
        float P[DIM];
        float tot = 0.f;
        #pragma unroll
        for (int mm = 0; mm < DIM; mm++) {
            P[mm] = Vre[kk][mm] * Vre[ll][mm] + Vim[kk][mm] * Vim[ll][mm];
            tot += P[mm];
        }
        #pragma unroll
        for (int i = 0; i < 4; i++) {
            float sub = 0.f;
            #pragma unroll
            for (int mm = 0; mm < DIM; mm++)
                if ((mm >> (3 - i)) & 1) sub += P[mm];
            Msh[tid][i] = tot - 2.f * sub;
        }
    }
    __syncthreads();

    // Expand into the 81-term basis via Msh lookups.
    for (int idx = tid; idx < 4 * NT3; idx += blockDim.x) {
        const int i = idx / NT3;
        const int t = idx % NT3;
        const int tq[4] = { t / 27, (t / 9) % 3, (t / 3) % 3, t % 3 };

        float acc = 0.f;
        for (int b = 0; b < 16; b++) {
            int kk = 0, ll = 0;
            float sgn = 1.f / 16.f;
            #pragma unroll
            for (int q = 0; q < 4; q++) {
                const int bq = (b >> q) & 1;
                const int sh = 3 - q;
                if (tq[q] == 2) {
                    kk |= bq << sh; ll |= (1 - bq) << sh;
                } else {
                    kk |= bq << sh; ll |= bq << sh;
                    if (tq[q] == 1 && bq) sgn = -sgn;
                }
            }
            acc += sgn * Msh[kk * DIM + ll][i];
        }
        ((float*)g_blob.C)[(h * NT3 + t) * 4 + i] = acc;
    }
}

// ---------------------------------------------------------------------------
// Main kernel: 2 tokens/thread, f32x2 packed over ev-index pairs.
// ALL table reads (C, W, bias) are warp-uniform accesses to __constant__,
// i.e. uniform LDC fetches: no 32-lane data replication, no L1tex wavefront
// queue pressure. Zero shared memory.
// ---------------------------------------------------------------------------
__global__ __launch_bounds__(BLK, 4) void qc_main_kernel(
    const float* __restrict__ x,
    float*       __restrict__ out,
    int ntok)
{
    const int tid  = threadIdx.x;
    const int tokA = blockIdx.x * (BLK * TPT) + tid;
    const int tokB = tokA + BLK;
    const bool okA = tokA < ntok, okB = tokB < ntok;

    u64 accA[16], accB[16];
    #pragma unroll
    for (int jp = 0; jp < 16; jp++) { accA[jp] = c_blob.b2[jp]; accB[jp] = accA[jp]; }

    u64 one2;
    PACK2(one2, 1.0f, 1.0f);

    const float4* xp4 = reinterpret_cast<const float4*>(x);

    #pragma unroll 1
    for (int h = 0; h < NH; h++) {
        float4 xa = okA ? xp4[(size_t)tokA * NH + h] : make_float4(0.f, 0.f, 0.f, 0.f);
        float4 xb = okB ? xp4[(size_t)tokB * NH + h] : make_float4(0.f, 0.f, 0.f, 0.f);

        // dup-packed trig basis: Ad[q][0]=(cos,cos), Ad[q][1]=(sin,sin)
        u64 Ad[4][2], Bd[4][2];
        {
            float c, s;
            __sincosf(xa.x, &s, &c); PACK2(Ad[0][0], c, c); PACK2(Ad[0][1], s, s);
            __sincosf(xa.y, &s, &c); PACK2(Ad[1][0], c, c); PACK2(Ad[1][1], s, s);
            __sincosf(xa.z, &s, &c); PACK2(Ad[2][0], c, c); PACK2(Ad[2][1], s, s);
            __sincosf(xa.w, &s, &c); PACK2(Ad[3][0], c, c); PACK2(Ad[3][1], s, s);
            __sincosf(xb.x, &s, &c); PACK2(Bd[0][0], c, c); PACK2(Bd[0][1], s, s);
            __sincosf(xb.y, &s, &c); PACK2(Bd[1][0], c, c); PACK2(Bd[1][1], s, s);
            __sincosf(xb.z, &s, &c); PACK2(Bd[2][0], c, c); PACK2(Bd[2][1], s, s);
            __sincosf(xb.w, &s, &c); PACK2(Bd[3][0], c, c); PACK2(Bd[3][1], s, s);
        }

        u64 evA01 = 0ull, evA23 = 0ull, evB01 = 0ull, evB23 = 0ull;

        int term = 0;
        #pragma unroll
        for (int a = 0; a < 3; a++) {
            u64 pA0 = one2, pB0 = one2;
            if (a > 0) { pA0 = Ad[0][a - 1]; pB0 = Bd[0][a - 1]; }
            #pragma unroll
            for (int b = 0; b < 3; b++) {
                u64 pA1, pB1;
                if (b == 0)      { pA1 = pA0;          pB1 = pB0; }
                else if (a == 0) { pA1 = Ad[1][b - 1]; pB1 = Bd[1][b - 1]; }
                else             { MUL2(pA1, pA0, Ad[1][b - 1]);
                                   MUL2(pB1, pB0, Bd[1][b - 1]); }
                #pragma unroll
                for (int c = 0; c < 3; c++) {
                    const bool v2 = (a | b) != 0;
                    u64 pA2, pB2;
                    if (c == 0)      { pA2 = pA1;          pB2 = pB1; }
                    else if (!v2)    { pA2 = Ad[2][c - 1]; pB2 = Bd[2][c - 1]; }
                    else             { MUL2(pA2, pA1, Ad[2][c - 1]);
                                       MUL2(pB2, pB1, Bd[2][c - 1]); }
                    #pragma unroll
                    for (int d = 0; d < 3; d++) {
                        const bool v3 = (a | b | c) != 0;
                        u64 phA, phB;
                        if (d == 0)      { phA = pA2;          phB = pB2; }
                        else if (!v3)    { phA = Ad[3][d - 1]; phB = Bd[3][d - 1]; }
                        else             { MUL2(phA, pA2, Ad[3][d - 1]);
                                           MUL2(phB, pB2, Bd[3][d - 1]); }
                        const ulonglong2 cc = c_blob.C[h * NT3 + term];   // uniform LDC
                        FMAX2(evA01, cc.x, phA, evA01);
                        FMAX2(evA23, cc.y, phA, evA23);
                        FMAX2(evB01, cc.x, phB, evB01);
                        FMAX2(evB23, cc.y, phB, evB23);
                        term++;
                    }
                }
            }
        }

        // Fold into j-packed accumulators; W comes from constant (uniform LDC).
        u64 dA[4], dB[4];
        {
            float e0, e1, e2, e3;
            UNPACK2(e0, e1, evA01); UNPACK2(e2, e3, evA23);
            PACK2(dA[0], e0, e0); PACK2(dA[1], e1, e1);
            PACK2(dA[2], e2, e2); PACK2(dA[3], e3, e3);
            UNPACK2(e0, e1, evB01); UNPACK2(e2, e3, evB23);
            PACK2(dB[0], e0, e0); PACK2(dB[1], e1, e1);
            PACK2(dB[2], e2, e2); PACK2(dB[3], e3, e3);
        }
        #pragma unroll
        for (int i = 0; i < 4; i++) {
            const u64 ai = dA[i], bi = dB[i];
            #pragma unroll
            for (int k = 0; k < 8; k++) {
                const ulonglong2 wd = c_blob.Wq[h * 32 + i * 8 + k];      // uniform LDC
                FMAX2(accA[2 * k],     wd.x, ai, accA[2 * k]);
                FMAX2(accA[2 * k + 1], wd.y, ai, accA[2 * k + 1]);
                FMAX2(accB[2 * k],     wd.x, bi, accB[2 * k]);
                FMAX2(accB[2 * k + 1], wd.y, bi, accB[2 * k + 1]);
            }
        }
    }

    if (okA) {
        ulonglong2* op = reinterpret_cast<ulonglong2*>(out + (size_t)tokA * EMB);
        #pragma unroll
        for (int jj = 0; jj < 8; jj++)
            op[jj] = make_ulonglong2(accA[2 * jj], accA[2 * jj + 1]);
    }
    if (okB) {
        ulonglong2* op = reinterpret_cast<ulonglong2*>(out + (size_t)tokB * EMB);
        #pragma unroll
        for (int jj = 0; jj < 8; jj++)
            op[jj] = make_ulonglong2(accB[2 * jj], accB[2 * jj + 1]);
    }
}

// ---------------------------------------------------------------------------
extern "C" void kernel_launch(void* const* d_in, const int* in_sizes, int n_in,
                              void* d_out, int out_size) {
    const float* x      = (const float*)d_in[0];
    const float* params = (const float*)d_in[1];
    const float* W      = (const float*)d_in[2];
    const float* b      = (const float*)d_in[3];
    float* out = (float*)d_out;

    const int ntok = in_sizes[0] / EMB;

    qc_setup_kernel<<<NH, 256>>>(params, W, b);

    // Blob -> __constant__ (device-to-device memcpy node; graph-capturable).
    void *src = nullptr, *dst = nullptr;
    cudaGetSymbolAddress(&src, g_blob);
    cudaGetSymbolAddress(&dst, c_blob);
    cudaMemcpyAsync(dst, src, sizeof(CBlob), cudaMemcpyDeviceToDevice, 0);

    const int tok_per_block = BLK * TPT;
    const int blocks = (ntok + tok_per_block - 1) / tok_per_block;
    qc_main_kernel<<<blocks, BLK>>>(x, out, ntok);
}